// round 6
// baseline (speedup 1.0000x reference)
#include <cuda_runtime.h>
#include <cuda_bf16.h>
#include <math.h>
#include <stdint.h>

// Problem constants
#define D_MODEL 1024
#define D_INNER 2048
#define D_STATE 16
#define DT_RANK 64
#define D_CONV  4
#define BB      2
#define LL      1024
#define BL      (BB * LL)                 // 2048 rows
#define KS      8                         // split-K for x_proj

// ---------------------------------------------------------------------------
// Device scratch (no cudaMalloc allowed)
// 3-segment split layout along K (K' = 3K):
//   activations: [hi | lo | hi]
//   weights:     [hi | hi | lo]
// so A'.W'^T = ahi*whi + alo*whi + ahi*wlo  (3-term compensated product)
// ---------------------------------------------------------------------------
__device__ float          g_xz[BL * 4096];          // in_proj out (f32)
__device__ float          g_xc[BL * 2048];          // conv out f32 (for scan)
__device__ __nv_bfloat16  g_xcs[BL * 6144];         // conv out, act-split K'=6144
__device__ float          g_xpart[KS * BL * 128];   // x_proj split-K partials
__device__ float          g_xdbl[BL * 128];         // x_proj out f32 (ld=128)
__device__ __nv_bfloat16  g_dtA[BL * 192];          // dt rows act-split K'=192
__device__ float          g_delta[BL * 2048];       // softplus'd delta
__device__ __nv_bfloat16  g_ys[BL * 6144];          // scan out act-split K'=6144
__device__ __nv_bfloat16  g_xs[BL * 3072];          // x act-split K'=3072
__device__ __nv_bfloat16  g_wi[4096 * 3072];        // in_proj_w wt-split
__device__ __nv_bfloat16  g_wo[1024 * 6144];        // out_proj_w wt-split
__device__ __nv_bfloat16  g_wx[128 * 6144];         // x_proj_w wt-split (pad 128 rows)
__device__ __nv_bfloat16  g_wdt[2048 * 192];        // dt_proj_w wt-split

// ---------------------------------------------------------------------------
// helpers
// ---------------------------------------------------------------------------
__device__ __forceinline__ void cvt_pair(float x, float y,
                                         uint32_t& hi, uint32_t& lo) {
    asm("cvt.rn.bf16x2.f32 %0, %1, %2;" : "=r"(hi) : "f"(y), "f"(x));
    const float hx = __uint_as_float(hi << 16);
    const float hy = __uint_as_float(hi & 0xFFFF0000u);
    asm("cvt.rn.bf16x2.f32 %0, %1, %2;" : "=r"(lo) : "f"(y - hy), "f"(x - hx));
}

__device__ __forceinline__ void cp16(uint32_t s, const void* g) {
    asm volatile("cp.async.cg.shared.global [%0], [%1], 16;" :: "r"(s), "l"(g));
}
__device__ __forceinline__ void cp_commit() {
    asm volatile("cp.async.commit_group;");
}
__device__ __forceinline__ void cp_wait1() {
    asm volatile("cp.async.wait_group 1;" ::: "memory");
}

#define LDSM_X4(r0, r1, r2, r3, addr) \
    asm volatile("ldmatrix.sync.aligned.m8n8.x4.shared.b16 {%0,%1,%2,%3}, [%4];" \
                 : "=r"(r0), "=r"(r1), "=r"(r2), "=r"(r3) : "r"(addr))

__device__ __forceinline__ void mma_bf16(float (&c)[4],
                                         uint32_t a0, uint32_t a1,
                                         uint32_t a2, uint32_t a3,
                                         uint32_t b0, uint32_t b1) {
    asm volatile(
        "mma.sync.aligned.m16n8k16.row.col.f32.bf16.bf16.f32 "
        "{%0,%1,%2,%3},{%4,%5,%6,%7},{%8,%9},{%0,%1,%2,%3};"
        : "+f"(c[0]), "+f"(c[1]), "+f"(c[2]), "+f"(c[3])
        : "r"(a0), "r"(a1), "r"(a2), "r"(a3), "r"(b0), "r"(b1));
}

// ---------------------------------------------------------------------------
// bf16 HGEMM (pre-split operands):
//   C[M,N] = A[M,K'](lda) * W[N,K'](ldw)^T,  bf16 in, f32 out.
// BM=BN=128, BK=64 bf16 (128B rows), 3-stage cp.async, ldmatrix, m16n8k16.
// 256 threads = 8 warps (2x4), warp tile 64x32.
// EPI==1: +bias then softplus. Split-K via blockIdx.z (k-offset z*T*64,
// C += z*czstride). Requires M%128==0, N%128==0, K'%64==0 per split.
// ---------------------------------------------------------------------------
template<int EPI>
__global__ void __launch_bounds__(256, 2)
hgemm(const __nv_bfloat16* __restrict__ A, const __nv_bfloat16* __restrict__ W,
      float* __restrict__ C, int lda, int ldw, int ldc, int T,
      long czstride, const float* __restrict__ bias)
{
    extern __shared__ __align__(16) char smem[];
    const uint32_t smA0 = (uint32_t)__cvta_generic_to_shared(smem);
    const uint32_t smB0 = smA0 + 3 * 16384;

    const int tid  = threadIdx.x;
    const int wid  = tid >> 5;
    const int lane = tid & 31;
    const int wm   = wid >> 2;        // 0..1
    const int wn   = wid & 3;         // 0..3
    const int l16  = lane & 15;
    const int chal = lane >> 4;       // 0,1

    const long blockM = (long)blockIdx.y * 128;
    const long blockN = (long)blockIdx.x * 128;
    const int  koff   = blockIdx.z * T * 64;

    const __nv_bfloat16* Ab = A + blockM * lda + koff;
    const __nv_bfloat16* Wb = W + blockN * ldw + koff;

    // cp.async mapping: 8 threads per 128B row, 4 row-passes
    const int crow = tid >> 3;        // 0..31
    const int ccc  = tid & 7;         // chunk col

    // ldmatrix fragment bases
    uint32_t aoff[4], asw[4], boff[2], bsw[2];
#pragma unroll
    for (int mi = 0; mi < 4; mi++) {
        const int r = wm * 64 + mi * 16 + l16;
        aoff[mi] = r * 128;
        asw[mi]  = r & 7;
    }
#pragma unroll
    for (int ni = 0; ni < 2; ni++) {
        const int r = wn * 32 + ni * 16 + l16;
        boff[ni] = r * 128;
        bsw[ni]  = r & 7;
    }

    float acc[4][4][4];
#pragma unroll
    for (int mi = 0; mi < 4; mi++)
#pragma unroll
        for (int n8 = 0; n8 < 4; n8++)
#pragma unroll
            for (int j = 0; j < 4; j++) acc[mi][n8][j] = 0.f;

    auto issue = [&](int s, int t) {
        const int k0 = t * 64;
        const uint32_t dA = smA0 + s * 16384;
        const uint32_t dB = smB0 + s * 16384;
#pragma unroll
        for (int p = 0; p < 4; p++) {
            const int row = crow + p * 32;
            const int scc = ccc ^ (row & 7);
            cp16(dA + row * 128 + scc * 16, Ab + (long)row * lda + k0 + ccc * 8);
            cp16(dB + row * 128 + scc * 16, Wb + (long)row * ldw + k0 + ccc * 8);
        }
    };

    // prologue: 2 stages
    if (0 < T) issue(0, 0);
    cp_commit();
    if (1 < T) issue(1, 1);
    cp_commit();

    for (int t = 0; t < T; t++) {
        cp_wait1();
        __syncthreads();
        const int nt = t + 2;
        if (nt < T) issue(nt % 3, nt);
        cp_commit();

        const uint32_t sA = smA0 + (t % 3) * 16384;
        const uint32_t sB = smB0 + (t % 3) * 16384;
#pragma unroll
        for (int k16 = 0; k16 < 4; k16++) {
            const uint32_t ch = (uint32_t)(k16 * 2 + chal);
            uint32_t a[4][4], b[2][4];
#pragma unroll
            for (int mi = 0; mi < 4; mi++)
                LDSM_X4(a[mi][0], a[mi][1], a[mi][2], a[mi][3],
                        sA + aoff[mi] + ((ch ^ asw[mi]) << 4));
#pragma unroll
            for (int ni = 0; ni < 2; ni++)
                LDSM_X4(b[ni][0], b[ni][1], b[ni][2], b[ni][3],
                        sB + boff[ni] + ((ch ^ bsw[ni]) << 4));
#pragma unroll
            for (int mi = 0; mi < 4; mi++)
#pragma unroll
                for (int n8 = 0; n8 < 4; n8++) {
                    const int np = n8 >> 1;
                    const uint32_t b0 = (n8 & 1) ? b[np][1] : b[np][0];
                    const uint32_t b1 = (n8 & 1) ? b[np][3] : b[np][2];
                    mma_bf16(acc[mi][n8],
                             a[mi][0], a[mi][1], a[mi][2], a[mi][3], b0, b1);
                }
        }
    }

    // epilogue
    float* Cb = C + (long)blockIdx.z * czstride;
    const int er = lane >> 2;
    const int ec = (lane & 3) * 2;
#pragma unroll
    for (int mi = 0; mi < 4; mi++) {
#pragma unroll
        for (int n8 = 0; n8 < 4; n8++) {
            const long row = blockM + wm * 64 + mi * 16 + er;
            const int  col = (int)blockN + wn * 32 + n8 * 8 + ec;
            float v0 = acc[mi][n8][0], v1 = acc[mi][n8][1];
            float v2 = acc[mi][n8][2], v3 = acc[mi][n8][3];
            if (EPI == 1) {
                const float b0 = bias[col], b1 = bias[col + 1];
                v0 += b0; v1 += b1; v2 += b0; v3 += b1;
                v0 = (v0 > 20.f) ? v0 : log1pf(expf(v0));
                v1 = (v1 > 20.f) ? v1 : log1pf(expf(v1));
                v2 = (v2 > 20.f) ? v2 : log1pf(expf(v2));
                v3 = (v3 > 20.f) ? v3 : log1pf(expf(v3));
            }
            *(float2*)&Cb[row * ldc + col]       = make_float2(v0, v1);
            *(float2*)&Cb[(row + 8) * ldc + col] = make_float2(v2, v3);
        }
    }
}

// ---------------------------------------------------------------------------
// f32 -> bf16 3-segment split, row stride 3K.
//   ACT==1 (activations): [hi | lo | hi]
//   ACT==0 (weights):     [hi | hi | lo]
// Rows >= inRows are zero-padded. n4 = outRows*K/4.
// ---------------------------------------------------------------------------
template<int ACT>
__global__ void split_kernel(const float* __restrict__ in,
                             __nv_bfloat16* __restrict__ out,
                             int K, int n4, int inRows)
{
    const int i = blockIdx.x * 256 + threadIdx.x;
    if (i >= n4) return;
    const int e   = i * 4;
    const int row = e / K;
    const int k   = e - row * K;
    float4 v = make_float4(0.f, 0.f, 0.f, 0.f);
    if (row < inRows) v = *(const float4*)(in + (long)row * K + k);
    uint32_t h01, l01, h23, l23;
    cvt_pair(v.x, v.y, h01, l01);
    cvt_pair(v.z, v.w, h23, l23);
    __nv_bfloat16* o = out + (long)row * 3 * K + k;
    const uint2 hv = make_uint2(h01, h23);
    const uint2 lv = make_uint2(l01, l23);
    if (ACT) {
        *(uint2*)o           = hv;
        *(uint2*)(o + K)     = lv;
        *(uint2*)(o + 2 * K) = hv;
    } else {
        *(uint2*)o           = hv;
        *(uint2*)(o + K)     = hv;
        *(uint2*)(o + 2 * K) = lv;
    }
}

// ---------------------------------------------------------------------------
// Split-K reduce for x_proj partials + dt-row act-split (K=64 -> [hi|lo|hi])
// ---------------------------------------------------------------------------
__global__ void reduce_split(const float* __restrict__ p,
                             float* __restrict__ xdbl,
                             __nv_bfloat16* __restrict__ dtA)
{
    const int n4 = BL * 128 / 4;
    const int i = blockIdx.x * 256 + threadIdx.x;
    if (i >= n4) return;
    float4 a = ((const float4*)p)[i];
#pragma unroll
    for (int s = 1; s < KS; s++) {
        const float4 b = ((const float4*)p)[(long)s * n4 + i];
        a.x += b.x; a.y += b.y; a.z += b.z; a.w += b.w;
    }
    ((float4*)xdbl)[i] = a;
    const int e = i * 4;
    const int col = e & 127;
    if (col < 64) {
        const int row = e >> 7;
        uint32_t h01, l01, h23, l23;
        cvt_pair(a.x, a.y, h01, l01);
        cvt_pair(a.z, a.w, h23, l23);
        __nv_bfloat16* o = dtA + (long)row * 192 + col;
        const uint2 hv = make_uint2(h01, h23);
        *(uint2*)o         = hv;
        *(uint2*)(o + 64)  = make_uint2(l01, l23);
        *(uint2*)(o + 128) = hv;
    }
}

// ---------------------------------------------------------------------------
// Depthwise causal conv (k=4) + bias + SiLU; writes f32 + act-split bf16
// ---------------------------------------------------------------------------
__global__ void conv_silu_kernel(const float* __restrict__ xz,
                                 const float* __restrict__ cw,
                                 const float* __restrict__ cb,
                                 float* __restrict__ xc,
                                 __nv_bfloat16* __restrict__ xcs)
{
    const int idx = blockIdx.x * blockDim.x + threadIdx.x;
    if (idx >= BL * D_INNER) return;
    const int d = idx & (D_INNER - 1);
    const int r = idx >> 11;             // row = b*LL + l
    const int l = r & (LL - 1);
    const int b = r >> 10;

    float acc = cb[d];
#pragma unroll
    for (int i = 0; i < D_CONV; i++) {
        const int ll = l - (D_CONV - 1) + i;
        if (ll >= 0)
            acc = fmaf(xz[((long)(b * LL + ll)) * 4096 + d],
                       cw[d * D_CONV + i], acc);
    }
    const float s = acc / (1.f + expf(-acc));
    xc[idx] = s;
    const __nv_bfloat16 h = __float2bfloat16(s);
    __nv_bfloat16* o = xcs + (long)r * 6144 + d;
    o[0]    = h;
    o[2048] = __float2bfloat16(s - __bfloat162float(h));
    o[4096] = h;
}

// ---------------------------------------------------------------------------
// Selective scan + D skip + SiLU(z) gating; writes y as act-split bf16
// ---------------------------------------------------------------------------
__global__ void scan_kernel(const float* __restrict__ delta,
                            const float* __restrict__ xdbl,
                            const float* __restrict__ xc,
                            const float* __restrict__ xz,
                            const float* __restrict__ A_log,
                            const float* __restrict__ Dv,
                            __nv_bfloat16* __restrict__ ys)
{
    const int t    = blockIdx.x * blockDim.x + threadIdx.x;
    const int lane = t & 15;
    const int g    = t >> 4;
    const int d    = g & (D_INNER - 1);
    const int b    = g >> 11;

    const float Aval = -expf(A_log[d * D_STATE + lane]);
    const float Dd   = Dv[d];

    const float* dp  = delta + ((long)b << 21) + d;
    const float* xcp = xc    + ((long)b << 21) + d;
    const float* xdp = xdbl  + (long)b * LL * 128;
    const float* zp  = xz    + ((long)b << 22) + D_INNER + d;

    float h = 0.f;
    for (int l = 0; l < LL; l++) {
        const float dl  = dp[(long)l << 11];
        const float xcv = xcp[(long)l << 11];
        const float Bv  = xdp[l * 128 + 64 + lane];
        const float Cv  = xdp[l * 128 + 80 + lane];

        const float dA = expf(dl * Aval);
        h = fmaf(dA, h, dl * Bv * xcv);

        float p = h * Cv;
        p += __shfl_xor_sync(0xffffffffu, p, 8);
        p += __shfl_xor_sync(0xffffffffu, p, 4);
        p += __shfl_xor_sync(0xffffffffu, p, 2);
        p += __shfl_xor_sync(0xffffffffu, p, 1);

        if (lane == 0) {
            const float zv  = zp[(long)l << 12];
            const float sig = 1.f / (1.f + expf(-zv));
            const float yv  = (p + xcv * Dd) * (zv * sig);
            const long  row = (long)b * LL + l;
            const __nv_bfloat16 hh = __float2bfloat16(yv);
            __nv_bfloat16* o = ys + row * 6144 + d;
            o[0]    = hh;
            o[2048] = __float2bfloat16(yv - __bfloat162float(hh));
            o[4096] = hh;
        }
    }
}

// ---------------------------------------------------------------------------
// Launch
// ---------------------------------------------------------------------------
extern "C" void kernel_launch(void* const* d_in, const int* in_sizes, int n_in,
                              void* d_out, int out_size)
{
    const float* x         = (const float*)d_in[0];
    const float* in_proj_w = (const float*)d_in[1];
    const float* conv_w    = (const float*)d_in[2];
    const float* conv_b    = (const float*)d_in[3];
    const float* x_proj_w  = (const float*)d_in[4];
    const float* dt_proj_w = (const float*)d_in[5];
    const float* dt_proj_b = (const float*)d_in[6];
    const float* A_log     = (const float*)d_in[7];
    const float* Dv        = (const float*)d_in[8];
    const float* out_proj  = (const float*)d_in[9];
    float* out = (float*)d_out;

    float *xz, *xc, *xpart, *xdbl, *delta;
    __nv_bfloat16 *xcs, *dtA, *ys, *xs, *wi, *wo, *wx, *wdt;
    cudaGetSymbolAddress((void**)&xz,    g_xz);
    cudaGetSymbolAddress((void**)&xc,    g_xc);
    cudaGetSymbolAddress((void**)&xcs,   g_xcs);
    cudaGetSymbolAddress((void**)&xpart, g_xpart);
    cudaGetSymbolAddress((void**)&xdbl,  g_xdbl);
    cudaGetSymbolAddress((void**)&dtA,   g_dtA);
    cudaGetSymbolAddress((void**)&delta, g_delta);
    cudaGetSymbolAddress((void**)&ys,    g_ys);
    cudaGetSymbolAddress((void**)&xs,    g_xs);
    cudaGetSymbolAddress((void**)&wi,    g_wi);
    cudaGetSymbolAddress((void**)&wo,    g_wo);
    cudaGetSymbolAddress((void**)&wx,    g_wx);
    cudaGetSymbolAddress((void**)&wdt,   g_wdt);

    const int SMEM_SZ = 6 * 16384;   // 96 KB
    static bool attr_set = false;
    if (!attr_set) {
        cudaFuncSetAttribute(hgemm<0>, cudaFuncAttributeMaxDynamicSharedMemorySize, SMEM_SZ);
        cudaFuncSetAttribute(hgemm<1>, cudaFuncAttributeMaxDynamicSharedMemorySize, SMEM_SZ);
        attr_set = true;
    }

    // 0. pre-splits (3-segment K-concat)
    split_kernel<1><<<(BL * 1024 / 4 + 255) / 256, 256>>>(x, xs, 1024, BL * 1024 / 4, BL);
    split_kernel<0><<<(4096 * 1024 / 4 + 255) / 256, 256>>>(in_proj_w, wi, 1024, 4096 * 1024 / 4, 4096);
    split_kernel<0><<<(1024 * 2048 / 4 + 255) / 256, 256>>>(out_proj, wo, 2048, 1024 * 2048 / 4, 1024);
    split_kernel<0><<<(128 * 2048 / 4 + 255) / 256, 256>>>(x_proj_w, wx, 2048, 128 * 2048 / 4, 96);
    split_kernel<0><<<(2048 * 64 / 4 + 255) / 256, 256>>>(dt_proj_w, wdt, 64, 2048 * 64 / 4, 2048);

    // 1. xz = x @ in_proj_w.T  (M=2048, N=4096, K'=3072)
    hgemm<0><<<dim3(32, 16, 1), 256, SMEM_SZ>>>(
        xs, wi, xz, 3072, 3072, 4096, 48, 0, nullptr);

    // 2. xc = silu(causal_conv(xi) + b)  (+ act-split)
    conv_silu_kernel<<<(BL * D_INNER + 255) / 256, 256>>>(xz, conv_w, conv_b, xc, xcs);

    // 3. x_dbl = xc @ x_proj_w.T  (M=2048, N=128pad, K'=6144), split-K=8
    hgemm<0><<<dim3(1, 16, KS), 256, SMEM_SZ>>>(
        xcs, wx, xpart, 6144, 6144, 128, 6144 / KS / 64, (long)BL * 128, nullptr);
    reduce_split<<<(BL * 128 / 4 + 255) / 256, 256>>>(xpart, xdbl, dtA);

    // 4. delta = softplus(dt @ dt_proj_w.T + b)  (M=2048, N=2048, K'=192)
    hgemm<1><<<dim3(16, 16, 1), 256, SMEM_SZ>>>(
        dtA, wdt, delta, 192, 192, 2048, 3, 0, dt_proj_b);

    // 5. selective scan + D skip + SiLU(z) gating (+ y act-split)
    scan_kernel<<<(BB * D_INNER * D_STATE) / 256, 256>>>(
        delta, xdbl, xc, xz, A_log, Dv, ys);

    // 6. out = y @ out_proj_w.T  (M=2048, N=1024, K'=6144)
    hgemm<0><<<dim3(8, 16, 1), 256, SMEM_SZ>>>(
        ys, wo, out, 6144, 6144, 1024, 96, 0, nullptr);
}